// round 2
// baseline (speedup 1.0000x reference)
#include <cuda_runtime.h>
#include <math.h>

// Problem constants
#define T_STEPS 1024
#define D_IN    2048
#define NH      2048
#define CATS    1000

// Recurrence kernel config
#define NBLK    128          // persistent blocks (1 block/SM, <= SM count)
#define NTH     256          // 8 warps
#define NWARP   8
#define HPB     16           // hidden indices owned per block (z AND ht)
#define RPB     32           // matvec rows per block (16 z + 16 ht)
#define NSTAGE  26           // rows of U pinned in SMEM per block
#define SMEM_FLOATS (NSTAGE*NH + NH + 32)
#define SMEM_BYTES  (SMEM_FLOATS * 4)

// Scratch (device globals; no allocation allowed)
__device__ float g_XZ[T_STEPS * NH];
__device__ float g_XH[T_STEPS * NH];
__device__ float g_P[2][NH];
__device__ float g_LOGITS[1024];
// Barrier flags: one padded slot (32B) per block; monotonic counts, wrap-safe.
__device__ volatile unsigned int g_flags[NBLK * 8];

// ---------------------------------------------------------------------------
// GEMM: C[t, n] = sum_k x[t,k] * W[n,k]; n<2048 -> Wz -> XZ, else Wh -> XH.
// ---------------------------------------------------------------------------
#define GBM 128
#define GBN 64
#define GBK 16

__global__ __launch_bounds__(256) void gemm_xproj(
    const float* __restrict__ x,
    const float* __restrict__ Wz,
    const float* __restrict__ Wh)
{
    __shared__ float As[GBK][GBM + 2];
    __shared__ float Bs[GBK][GBN + 2];

    const int tid  = threadIdx.x;
    const int row0 = blockIdx.y * GBM;
    const int col0 = blockIdx.x * GBN;

    const float* Bbase = (col0 < NH) ? (Wz + (size_t)col0 * D_IN)
                                     : (Wh + (size_t)(col0 - NH) * D_IN);

    const int trow = tid >> 4;
    const int tcol = tid & 15;
    const int m0 = trow * 8;
    const int n0 = tcol * 4;

    float acc[8][4];
    #pragma unroll
    for (int i = 0; i < 8; i++)
        #pragma unroll
        for (int j = 0; j < 4; j++) acc[i][j] = 0.f;

    for (int kt = 0; kt < D_IN; kt += GBK) {
        #pragma unroll
        for (int u = 0; u < 2; u++) {
            int idx = tid + u * 256;
            int ar  = idx >> 2;
            int ac4 = idx & 3;
            float4 v = *(const float4*)(x + (size_t)(row0 + ar) * D_IN + kt + ac4 * 4);
            As[ac4 * 4 + 0][ar] = v.x;
            As[ac4 * 4 + 1][ar] = v.y;
            As[ac4 * 4 + 2][ar] = v.z;
            As[ac4 * 4 + 3][ar] = v.w;
        }
        {
            int br  = tid >> 2;
            int bc4 = tid & 3;
            float4 v = *(const float4*)(Bbase + (size_t)br * D_IN + kt + bc4 * 4);
            Bs[bc4 * 4 + 0][br] = v.x;
            Bs[bc4 * 4 + 1][br] = v.y;
            Bs[bc4 * 4 + 2][br] = v.z;
            Bs[bc4 * 4 + 3][br] = v.w;
        }
        __syncthreads();

        #pragma unroll
        for (int k = 0; k < GBK; k++) {
            float a[8], bb[4];
            #pragma unroll
            for (int i = 0; i < 8; i++) a[i] = As[k][m0 + i];
            #pragma unroll
            for (int j = 0; j < 4; j++) bb[j] = Bs[k][n0 + j];
            #pragma unroll
            for (int i = 0; i < 8; i++)
                #pragma unroll
                for (int j = 0; j < 4; j++) acc[i][j] += a[i] * bb[j];
        }
        __syncthreads();
    }

    #pragma unroll
    for (int i = 0; i < 8; i++) {
        int t = row0 + m0 + i;
        #pragma unroll
        for (int j = 0; j < 4; j++) {
            int n = col0 + n0 + j;
            if (n < NH) g_XZ[(size_t)t * NH + n] = acc[i][j];
            else        g_XH[(size_t)t * NH + (n - NH)] = acc[i][j];
        }
    }
}

// ---------------------------------------------------------------------------
// Leaderless flag barrier: block stores its count to its own slot (no atomic
// contention), warp 0 of every block polls all slots. Wrap-safe compare.
// ---------------------------------------------------------------------------
__device__ __forceinline__ void flag_barrier(int b, unsigned int target)
{
    __syncthreads();
    if (threadIdx.x < 32) {
        if (threadIdx.x == 0) {
            __threadfence();            // order prior global stores before flag
            g_flags[b * 8] = target;    // volatile store
        }
        for (;;) {
            bool ok = true;
            #pragma unroll
            for (int u = 0; u < 4; u++) {
                unsigned int v = g_flags[(threadIdx.x + u * 32) * 8];
                if ((int)(v - target) < 0) ok = false;
            }
            if (__all_sync(0xffffffffu, ok)) break;
        }
        __threadfence();                // acquire: order flag reads before data reads
    }
    __syncthreads();
}

// ---------------------------------------------------------------------------
// Persistent recurrence. Block b owns hidden indices [16b, 16b+16) for BOTH
// gates: matvec row s in [0,16) -> z row 16b+s, s in [16,32) -> ht row 16b+s-16.
// Gates (z, ht) live only in block-local SMEM; only p is globally exchanged.
// ---------------------------------------------------------------------------
__global__ __launch_bounds__(NTH, 1) void gru_recurrence(
    const float* __restrict__ Uz, const float* __restrict__ Uh,
    const float* __restrict__ bz,
    const float* __restrict__ Wout,
    const float* __restrict__ zt0, const float* __restrict__ htilde0,
    const float* __restrict__ hprev0,
    float* __restrict__ out)
{
    extern __shared__ float sm[];
    float* smU = sm;                  // NSTAGE * NH
    float* ps  = sm + NSTAGE * NH;    // NH (p staging)
    float* sz  = ps + NH;             // 16 (stale z, local)
    float* sht = sz + 16;             // 16 (stale htilde, local)

    const int tid  = threadIdx.x;
    const int w    = tid >> 5;
    const int lane = tid & 31;
    const int b    = blockIdx.x;
    const int I0   = b * HPB;         // owned hidden index base

    unsigned int bar = g_flags[b * 8];   // launch-start count (same for all blocks)

    // Pin NSTAGE matvec rows into SMEM (once).  Row s: s<16 -> Uz[I0+s], else Uh[I0+s-16].
    for (int s = 0; s < NSTAGE; s++) {
        const float* src = (s < 16) ? (Uz + (size_t)(I0 + s) * NH)
                                    : (Uh + (size_t)(I0 + s - 16) * NH);
        for (int i = tid; i < NH / 4; i += NTH)
            ((float4*)(smU + (size_t)s * NH))[i] = ((const float4*)src)[i];
    }

    // Init local stale gates
    if (tid < 16) {
        sz[tid]  = zt0[I0 + tid];
        sht[tid] = htilde0[I0 + tid];
    }

    // Per-warp row assignment: s = w + 8*it, it in 0..3  (2 z rows + 2 ht rows)
    // Preload bias for the two z rows this warp owns.
    float bzv0 = 0.f, bzv1 = 0.f;
    if (lane == 0) {
        bzv0 = bz[I0 + w];       // s = w       (z)
        bzv1 = bz[I0 + w + 8];   // s = w + 8   (z)
    }
    __syncthreads();   // smU + gate init visible block-wide (no grid sync needed)

    for (int t = 0; t < T_STEPS; t++) {
        const float* Pc = (t == 0) ? hprev0 : g_P[t & 1];
        float* Pn = g_P[(t + 1) & 1];

        // Prefetch xz/xh for this step's rows (used after the matvec)
        float xv[4];
        if (lane == 0) {
            xv[0] = __ldg(&g_XZ[(size_t)t * NH + I0 + w]);
            xv[1] = __ldg(&g_XZ[(size_t)t * NH + I0 + w + 8]);
            xv[2] = __ldg(&g_XH[(size_t)t * NH + I0 + w]);
            xv[3] = __ldg(&g_XH[(size_t)t * NH + I0 + w + 8]);
        }

        // p' for owned indices, stored EARLY so it propagates during the matvec.
        if (tid < 16) {
            int i = I0 + tid;
            float p = __ldcg(&Pc[i]);
            float z = sz[tid], ht = sht[tid];
            Pn[i] = (1.f - z) * p + z * ht;
        }

        // Stage full p into SMEM (bypass L1; written by other SMs last step)
        #pragma unroll
        for (int u = 0; u < 2; u++) {
            int i = tid + u * NTH;
            ((float4*)ps)[i] = __ldcg((const float4*)Pc + i);
        }
        __syncthreads();

        // p -> registers (64 regs/lane)
        float4 preg[16];
        #pragma unroll
        for (int j = 0; j < 16; j++) preg[j] = ((const float4*)ps)[j * 32 + lane];

        // 4 matvec rows per warp
        #pragma unroll
        for (int it = 0; it < 4; it++) {
            const int s = w + 8 * it;
            float acc = 0.f;
            if (s < NSTAGE) {
                const float4* u4 = (const float4*)(smU + (size_t)s * NH);
                #pragma unroll
                for (int j = 0; j < 16; j++) {
                    float4 u = u4[j * 32 + lane];
                    acc += u.x * preg[j].x + u.y * preg[j].y
                         + u.z * preg[j].z + u.w * preg[j].w;
                }
            } else {
                const float* src = (s < 16) ? (Uz + (size_t)(I0 + s) * NH)
                                            : (Uh + (size_t)(I0 + s - 16) * NH);
                const float4* u4 = (const float4*)src;
                #pragma unroll
                for (int j = 0; j < 16; j++) {
                    float4 u = __ldg(u4 + j * 32 + lane);
                    acc += u.x * preg[j].x + u.y * preg[j].y
                         + u.z * preg[j].z + u.w * preg[j].w;
                }
            }
            #pragma unroll
            for (int off = 16; off; off >>= 1)
                acc += __shfl_xor_sync(0xffffffffu, acc, off);
            if (lane == 0) {
                if (it == 0) {          // s = w: z row
                    float pre = xv[0] + acc + bzv0;
                    sz[w] = 1.f / (1.f + expf(-pre));
                } else if (it == 1) {   // s = w+8: z row
                    float pre = xv[1] + acc + bzv1;
                    sz[w + 8] = 1.f / (1.f + expf(-pre));
                } else if (it == 2) {   // s = w+16: ht row (idx I0+w)
                    sht[w] = tanhf(xv[2] + acc);
                } else {                // s = w+24: ht row (idx I0+w+8)
                    sht[w + 8] = tanhf(xv[3] + acc);
                }
            }
        }

        flag_barrier(b, ++bar);   // all p_{t+1} stores visible chip-wide
    }

    // h_final = g_P[0] (p_1024). Logits: warp gw = b*8+w covers 1000 rows.
    {
        const float* Pf = g_P[0];
        #pragma unroll
        for (int u = 0; u < 2; u++) {
            int i = tid + u * NTH;
            ((float4*)ps)[i] = __ldcg((const float4*)Pf + i);
        }
        __syncthreads();
        float4 preg[16];
        #pragma unroll
        for (int j = 0; j < 16; j++) preg[j] = ((const float4*)ps)[j * 32 + lane];

        int gw = b * NWARP + w;
        if (gw < CATS) {
            const float4* u4 = (const float4*)(Wout + (size_t)gw * NH);
            float acc = 0.f;
            #pragma unroll
            for (int j = 0; j < 16; j++) {
                float4 u = __ldg(u4 + j * 32 + lane);
                acc += u.x * preg[j].x + u.y * preg[j].y
                     + u.z * preg[j].z + u.w * preg[j].w;
            }
            #pragma unroll
            for (int off = 16; off; off >>= 1)
                acc += __shfl_xor_sync(0xffffffffu, acc, off);
            if (lane == 0) g_LOGITS[gw] = acc;
        }
    }
    flag_barrier(b, ++bar);

    // Softmax in block 0
    if (b == 0) {
        __shared__ float red[NTH];
        float lm = -1e30f;
        for (int c = tid; c < CATS; c += NTH) lm = fmaxf(lm, __ldcg(&g_LOGITS[c]));
        red[tid] = lm; __syncthreads();
        for (int o = NTH / 2; o; o >>= 1) {
            if (tid < o) red[tid] = fmaxf(red[tid], red[tid + o]);
            __syncthreads();
        }
        float mx = red[0]; __syncthreads();
        float ls = 0.f;
        for (int c = tid; c < CATS; c += NTH) ls += expf(__ldcg(&g_LOGITS[c]) - mx);
        red[tid] = ls; __syncthreads();
        for (int o = NTH / 2; o; o >>= 1) {
            if (tid < o) red[tid] += red[tid + o];
            __syncthreads();
        }
        float inv = 1.f / red[0];
        for (int c = tid; c < CATS; c += NTH)
            out[c] = expf(__ldcg(&g_LOGITS[c]) - mx) * inv;
    }
}

// ---------------------------------------------------------------------------
extern "C" void kernel_launch(void* const* d_in, const int* in_sizes, int n_in,
                              void* d_out, int out_size)
{
    const float* x       = (const float*)d_in[0];
    const float* Wh      = (const float*)d_in[1];
    const float* Wz      = (const float*)d_in[2];
    // d_in[3] = Wr, d_in[7] = Ur, d_in[8] = br: dead code in reference
    const float* Uh      = (const float*)d_in[4];
    const float* Uz      = (const float*)d_in[5];
    const float* bz      = (const float*)d_in[6];
    const float* Wout    = (const float*)d_in[9];
    // d_in[10] = h0: never read by the reference recurrence
    const float* zt0     = (const float*)d_in[11];
    const float* htilde0 = (const float*)d_in[12];
    const float* hprev0  = (const float*)d_in[13];
    float* out = (float*)d_out;

    dim3 ggrid((NH * 2) / GBN, T_STEPS / GBM);
    gemm_xproj<<<ggrid, 256>>>(x, Wz, Wh);

    cudaFuncSetAttribute(gru_recurrence,
                         cudaFuncAttributeMaxDynamicSharedMemorySize, SMEM_BYTES);
    gru_recurrence<<<NBLK, NTH, SMEM_BYTES>>>(Uz, Uh, bz, Wout,
                                              zt0, htilde0, hprev0, out);
}

// round 3
// speedup vs baseline: 1.7405x; 1.7405x over previous
#include <cuda_runtime.h>
#include <math.h>

// Problem constants
#define T_STEPS 1024
#define D_IN    2048
#define NH      2048
#define CATS    1000

// Recurrence kernel config
#define NBLK    128          // persistent blocks (1 block/SM)
#define NTH     512          // 16 warps
#define HPB     16           // hidden indices owned per block (z AND ht)
#define NSTAGE  27           // rows of U pinned in SMEM per block (of 32)
// smem: U rows + p stage + partials + gates
#define SMEM_FLOATS (NSTAGE*NH + NH + 64 + 32)
#define SMEM_BYTES  (SMEM_FLOATS * 4)

// Scratch (device globals; no allocation allowed)
__device__ float g_XZ[T_STEPS * NH];
__device__ float g_XH[T_STEPS * NH];
__device__ float g_P[2][NH];
__device__ float g_LOGITS[1024];
__device__ unsigned int g_count;   // returns to 0 each launch
__device__ unsigned int g_gen;     // monotonic; equality-compared (wrap-safe)

// ---------------------------------------------------------------------------
// GEMM: C[t, n] = sum_k x[t,k] * W[n,k]; n<2048 -> Wz -> XZ, else Wh -> XH.
// ---------------------------------------------------------------------------
#define GBM 128
#define GBN 64
#define GBK 16

__global__ __launch_bounds__(256) void gemm_xproj(
    const float* __restrict__ x,
    const float* __restrict__ Wz,
    const float* __restrict__ Wh)
{
    __shared__ float As[GBK][GBM + 2];
    __shared__ float Bs[GBK][GBN + 2];

    const int tid  = threadIdx.x;
    const int row0 = blockIdx.y * GBM;
    const int col0 = blockIdx.x * GBN;

    const float* Bbase = (col0 < NH) ? (Wz + (size_t)col0 * D_IN)
                                     : (Wh + (size_t)(col0 - NH) * D_IN);

    const int trow = tid >> 4;
    const int tcol = tid & 15;
    const int m0 = trow * 8;
    const int n0 = tcol * 4;

    float acc[8][4];
    #pragma unroll
    for (int i = 0; i < 8; i++)
        #pragma unroll
        for (int j = 0; j < 4; j++) acc[i][j] = 0.f;

    for (int kt = 0; kt < D_IN; kt += GBK) {
        #pragma unroll
        for (int u = 0; u < 2; u++) {
            int idx = tid + u * 256;
            int ar  = idx >> 2;
            int ac4 = idx & 3;
            float4 v = *(const float4*)(x + (size_t)(row0 + ar) * D_IN + kt + ac4 * 4);
            As[ac4 * 4 + 0][ar] = v.x;
            As[ac4 * 4 + 1][ar] = v.y;
            As[ac4 * 4 + 2][ar] = v.z;
            As[ac4 * 4 + 3][ar] = v.w;
        }
        {
            int br  = tid >> 2;
            int bc4 = tid & 3;
            float4 v = *(const float4*)(Bbase + (size_t)br * D_IN + kt + bc4 * 4);
            Bs[bc4 * 4 + 0][br] = v.x;
            Bs[bc4 * 4 + 1][br] = v.y;
            Bs[bc4 * 4 + 2][br] = v.z;
            Bs[bc4 * 4 + 3][br] = v.w;
        }
        __syncthreads();

        #pragma unroll
        for (int k = 0; k < GBK; k++) {
            float a[8], bb[4];
            #pragma unroll
            for (int i = 0; i < 8; i++) a[i] = As[k][m0 + i];
            #pragma unroll
            for (int j = 0; j < 4; j++) bb[j] = Bs[k][n0 + j];
            #pragma unroll
            for (int i = 0; i < 8; i++)
                #pragma unroll
                for (int j = 0; j < 4; j++) acc[i][j] += a[i] * bb[j];
        }
        __syncthreads();
    }

    #pragma unroll
    for (int i = 0; i < 8; i++) {
        int t = row0 + m0 + i;
        #pragma unroll
        for (int j = 0; j < 4; j++) {
            int n = col0 + n0 + j;
            if (n < NH) g_XZ[(size_t)t * NH + n] = acc[i][j];
            else        g_XH[(size_t)t * NH + (n - NH)] = acc[i][j];
        }
    }
}

// ---------------------------------------------------------------------------
// Single-counter atomic + generation-broadcast barrier (round-1 proven).
// ---------------------------------------------------------------------------
__device__ __forceinline__ void grid_sync()
{
    __syncthreads();
    if (threadIdx.x == 0) {
        volatile unsigned int* genp = &g_gen;
        unsigned int gen = *genp;
        __threadfence();
        if (atomicAdd(&g_count, 1u) == NBLK - 1) {
            g_count = 0;
            __threadfence();
            *genp = gen + 1;
        } else {
            while (*genp == gen) { }
            __threadfence();
        }
    }
    __syncthreads();
}

// ---------------------------------------------------------------------------
// Persistent recurrence. Block b owns hidden indices [16b,16b+16) for both
// gates. Matvec rows: s in [0,16) -> z row I0+s, s in [16,32) -> ht row
// I0+s-16. K split across warp halves: warps 0-7 do K[0:1024), warps 8-15 do
// K[1024:2048). Warp (w'=w&7, kh=w>>3) handles half-rows s = w', w'+8,
// w'+16, w'+24. Rows s>=NSTAGE stream from global, prefetched into regs.
// ---------------------------------------------------------------------------
__global__ __launch_bounds__(NTH, 1) void gru_recurrence(
    const float* __restrict__ Uz, const float* __restrict__ Uh,
    const float* __restrict__ bz,
    const float* __restrict__ Wout,
    const float* __restrict__ zt0, const float* __restrict__ htilde0,
    const float* __restrict__ hprev0,
    float* __restrict__ out)
{
    extern __shared__ float sm[];
    float* smU   = sm;                   // NSTAGE * NH
    float* ps    = sm + NSTAGE * NH;     // NH (p staging)
    float* part0 = ps + NH;              // 32 partial sums, K-half 0
    float* part1 = part0 + 32;           // 32 partial sums, K-half 1
    float* sz    = part1 + 32;           // 16 stale z (block-local)
    float* sht   = sz + 16;              // 16 stale htilde

    const int tid  = threadIdx.x;
    const int w    = tid >> 5;
    const int lane = tid & 31;
    const int wp   = w & 7;              // row-group id
    const int kh   = w >> 3;             // K half
    const int b    = blockIdx.x;
    const int I0   = b * HPB;

    // Pin NSTAGE matvec rows into SMEM. Row s: s<16 -> Uz[I0+s], else Uh[I0+s-16].
    for (int s = 0; s < NSTAGE; s++) {
        const float* src = (s < 16) ? (Uz + (size_t)(I0 + s) * NH)
                                    : (Uh + (size_t)(I0 + s - 16) * NH);
        for (int i = tid; i < NH / 4; i += NTH)
            ((float4*)(smU + (size_t)s * NH))[i] = ((const float4*)src)[i];
    }
    if (tid < 16) {
        sz[tid]  = zt0[I0 + tid];
        sht[tid] = htilde0[I0 + tid];
    }
    float bzv = (tid < 16) ? bz[I0 + tid] : 0.f;
    __syncthreads();

    // Per-warp row setup
    const int s3 = wp + 24;                      // only it=3 can be residual
    const bool resid = (s3 >= NSTAGE);
    const float4* r0 = (const float4*)(smU + (size_t)(wp)      * NH + kh * 1024);
    const float4* r1 = (const float4*)(smU + (size_t)(wp + 8)  * NH + kh * 1024);
    const float4* r2 = (const float4*)(smU + (size_t)(wp + 16) * NH + kh * 1024);
    const float4* r3s = resid ? (const float4*)(Uh + (size_t)(I0 + s3 - 16) * NH + kh * 1024)
                              : (const float4*)(smU + (size_t)s3 * NH + kh * 1024);
    float4* ps4 = (float4*)ps;

    for (int t = 0; t < T_STEPS; t++) {
        const float* Pc = (t == 0) ? hprev0 : g_P[t & 1];
        float* Pn = g_P[(t + 1) & 1];

        // Prefetch residual U row into registers (constant; overlaps everything)
        float4 upre[8];
        if (resid) {
            #pragma unroll
            for (int j = 0; j < 8; j++) upre[j] = __ldg(r3s + j * 32 + lane);
        }

        // Per-row x projections for this step (threads 0..31, one row each)
        float xvv = 0.f;
        if (tid < 32) {
            xvv = (tid < 16) ? __ldg(&g_XZ[(size_t)t * NH + I0 + tid])
                             : __ldg(&g_XH[(size_t)t * NH + I0 + tid - 16]);
        }

        // p' for owned indices, stored EARLY (propagates during the matvec)
        if (tid < 16) {
            int i = I0 + tid;
            float p = __ldcg(&Pc[i]);
            Pn[i] = (1.f - sz[tid]) * p + sz[tid] * sht[tid];
        }

        // Stage full p into SMEM (one float4 per thread; bypass L1)
        ps4[tid] = __ldcg((const float4*)Pc + tid);
        __syncthreads();

        // p half -> registers (32 regs/lane)
        float4 preg[8];
        #pragma unroll
        for (int j = 0; j < 8; j++) preg[j] = ps4[kh * 256 + j * 32 + lane];

        // 4 half-row dots, interleaved for ILP
        float a0 = 0.f, a1 = 0.f, a2 = 0.f, a3 = 0.f;
        #pragma unroll
        for (int j = 0; j < 8; j++) {
            float4 p = preg[j];
            float4 u;
            u = r0[j * 32 + lane];
            a0 += u.x * p.x + u.y * p.y + u.z * p.z + u.w * p.w;
            u = r1[j * 32 + lane];
            a1 += u.x * p.x + u.y * p.y + u.z * p.z + u.w * p.w;
            u = r2[j * 32 + lane];
            a2 += u.x * p.x + u.y * p.y + u.z * p.z + u.w * p.w;
            u = resid ? upre[j] : r3s[j * 32 + lane];
            a3 += u.x * p.x + u.y * p.y + u.z * p.z + u.w * p.w;
        }
        #pragma unroll
        for (int off = 16; off; off >>= 1) {
            a0 += __shfl_xor_sync(0xffffffffu, a0, off);
            a1 += __shfl_xor_sync(0xffffffffu, a1, off);
            a2 += __shfl_xor_sync(0xffffffffu, a2, off);
            a3 += __shfl_xor_sync(0xffffffffu, a3, off);
        }
        if (lane == 0) {
            float* pt = kh ? part1 : part0;
            pt[wp]      = a0;
            pt[wp + 8]  = a1;
            pt[wp + 16] = a2;
            pt[wp + 24] = a3;
        }
        __syncthreads();

        // Gates (one warp): thread s handles row s
        if (tid < 32) {
            float v = part0[tid] + part1[tid];
            if (tid < 16) {
                float pre = xvv + v + bzv;
                sz[tid] = 1.f / (1.f + expf(-pre));
            } else {
                sht[tid - 16] = tanhf(xvv + v);
            }
        }

        grid_sync();   // all p_{t+1} stores visible chip-wide
    }

    // h_final = g_P[0] (p_1024). Logits: warp gw = b*16 + w.
    {
        ps4[tid] = __ldcg((const float4*)g_P[0] + tid);
        __syncthreads();

        int gw = b * 16 + w;
        if (gw < CATS) {
            const float4* u4 = (const float4*)(Wout + (size_t)gw * NH);
            float acc = 0.f;
            #pragma unroll
            for (int j = 0; j < 16; j++) {
                float4 u = __ldg(u4 + j * 32 + lane);
                float4 p = ps4[j * 32 + lane];
                acc += u.x * p.x + u.y * p.y + u.z * p.z + u.w * p.w;
            }
            #pragma unroll
            for (int off = 16; off; off >>= 1)
                acc += __shfl_xor_sync(0xffffffffu, acc, off);
            if (lane == 0) g_LOGITS[gw] = acc;
        }
    }
    grid_sync();

    // Softmax in block 0 (reduction buffer reuses ps)
    if (b == 0) {
        float* red = ps;
        float lm = -1e30f;
        for (int c = tid; c < CATS; c += NTH) lm = fmaxf(lm, __ldcg(&g_LOGITS[c]));
        red[tid] = lm; __syncthreads();
        for (int o = NTH / 2; o; o >>= 1) {
            if (tid < o) red[tid] = fmaxf(red[tid], red[tid + o]);
            __syncthreads();
        }
        float mx = red[0]; __syncthreads();
        float ls = 0.f;
        for (int c = tid; c < CATS; c += NTH) ls += expf(__ldcg(&g_LOGITS[c]) - mx);
        red[tid] = ls; __syncthreads();
        for (int o = NTH / 2; o; o >>= 1) {
            if (tid < o) red[tid] += red[tid + o];
            __syncthreads();
        }
        float inv = 1.f / red[0];
        for (int c = tid; c < CATS; c += NTH)
            out[c] = expf(__ldcg(&g_LOGITS[c]) - mx) * inv;
    }
}

// ---------------------------------------------------------------------------
extern "C" void kernel_launch(void* const* d_in, const int* in_sizes, int n_in,
                              void* d_out, int out_size)
{
    const float* x       = (const float*)d_in[0];
    const float* Wh      = (const float*)d_in[1];
    const float* Wz      = (const float*)d_in[2];
    // d_in[3] = Wr, d_in[7] = Ur, d_in[8] = br: dead code in reference
    const float* Uh      = (const float*)d_in[4];
    const float* Uz      = (const float*)d_in[5];
    const float* bz      = (const float*)d_in[6];
    const float* Wout    = (const float*)d_in[9];
    // d_in[10] = h0: never read by the reference recurrence
    const float* zt0     = (const float*)d_in[11];
    const float* htilde0 = (const float*)d_in[12];
    const float* hprev0  = (const float*)d_in[13];
    float* out = (float*)d_out;

    dim3 ggrid((NH * 2) / GBN, T_STEPS / GBM);
    gemm_xproj<<<ggrid, 256>>>(x, Wz, Wh);

    cudaFuncSetAttribute(gru_recurrence,
                         cudaFuncAttributeMaxDynamicSharedMemorySize, SMEM_BYTES);
    gru_recurrence<<<NBLK, NTH, SMEM_BYTES>>>(Uz, Uh, bz, Wout,
                                              zt0, htilde0, hprev0, out);
}

// round 4
// speedup vs baseline: 2.0122x; 1.1561x over previous
#include <cuda_runtime.h>
#include <math.h>

// Problem constants
#define T_STEPS 1024
#define D_IN    2048
#define NH      2048
#define CATS    1000

// Recurrence kernel config
#define NBLK    128          // persistent blocks (1 block/SM)
#define NTH     512          // 16 warps
#define HPB     16           // hidden indices owned per block (z AND ht)
#define NSTAGE  27           // rows of U pinned in SMEM per block (of 32)
// smem: U rows + p (block-local, persistent) + partials
#define SMEM_FLOATS (NSTAGE*NH + NH + 64)
#define SMEM_BYTES  (SMEM_FLOATS * 4)

// Scratch (device globals; no allocation allowed)
__device__ float g_XZ[T_STEPS * NH];
__device__ float g_XH[T_STEPS * NH];
__device__ float g_Zb[4][NH];      // gate z, 4-deep ring by generation&3
__device__ float g_HTb[4][NH];     // gate htilde
__device__ float g_LOGITS[1024];
__device__ unsigned int g_count;   // returns to 0 each barrier
__device__ unsigned int g_gen;     // monotonic; equality-compared (wrap-safe)

// ---------------------------------------------------------------------------
// GEMM: C[t, n] = sum_k x[t,k] * W[n,k]; n<2048 -> Wz -> XZ, else Wh -> XH.
// ---------------------------------------------------------------------------
#define GBM 128
#define GBN 64
#define GBK 16

__global__ __launch_bounds__(256) void gemm_xproj(
    const float* __restrict__ x,
    const float* __restrict__ Wz,
    const float* __restrict__ Wh)
{
    __shared__ float As[GBK][GBM + 2];
    __shared__ float Bs[GBK][GBN + 2];

    const int tid  = threadIdx.x;
    const int row0 = blockIdx.y * GBM;
    const int col0 = blockIdx.x * GBN;

    const float* Bbase = (col0 < NH) ? (Wz + (size_t)col0 * D_IN)
                                     : (Wh + (size_t)(col0 - NH) * D_IN);

    const int trow = tid >> 4;
    const int tcol = tid & 15;
    const int m0 = trow * 8;
    const int n0 = tcol * 4;

    float acc[8][4];
    #pragma unroll
    for (int i = 0; i < 8; i++)
        #pragma unroll
        for (int j = 0; j < 4; j++) acc[i][j] = 0.f;

    for (int kt = 0; kt < D_IN; kt += GBK) {
        #pragma unroll
        for (int u = 0; u < 2; u++) {
            int idx = tid + u * 256;
            int ar  = idx >> 2;
            int ac4 = idx & 3;
            float4 v = *(const float4*)(x + (size_t)(row0 + ar) * D_IN + kt + ac4 * 4);
            As[ac4 * 4 + 0][ar] = v.x;
            As[ac4 * 4 + 1][ar] = v.y;
            As[ac4 * 4 + 2][ar] = v.z;
            As[ac4 * 4 + 3][ar] = v.w;
        }
        {
            int br  = tid >> 2;
            int bc4 = tid & 3;
            float4 v = *(const float4*)(Bbase + (size_t)br * D_IN + kt + bc4 * 4);
            Bs[bc4 * 4 + 0][br] = v.x;
            Bs[bc4 * 4 + 1][br] = v.y;
            Bs[bc4 * 4 + 2][br] = v.z;
            Bs[bc4 * 4 + 3][br] = v.w;
        }
        __syncthreads();

        #pragma unroll
        for (int k = 0; k < GBK; k++) {
            float a[8], bb[4];
            #pragma unroll
            for (int i = 0; i < 8; i++) a[i] = As[k][m0 + i];
            #pragma unroll
            for (int j = 0; j < 4; j++) bb[j] = Bs[k][n0 + j];
            #pragma unroll
            for (int i = 0; i < 8; i++)
                #pragma unroll
                for (int j = 0; j < 4; j++) acc[i][j] += a[i] * bb[j];
        }
        __syncthreads();
    }

    #pragma unroll
    for (int i = 0; i < 8; i++) {
        int t = row0 + m0 + i;
        #pragma unroll
        for (int j = 0; j < 4; j++) {
            int n = col0 + n0 + j;
            if (n < NH) g_XZ[(size_t)t * NH + n] = acc[i][j];
            else        g_XH[(size_t)t * NH + (n - NH)] = acc[i][j];
        }
    }
}

// ---------------------------------------------------------------------------
// Grid barrier: single atomic counter + generation broadcast, release/acquire
// semantics (no MEMBAR.GL). Count returns to 0 each barrier; gen monotonic.
// ---------------------------------------------------------------------------
__device__ __forceinline__ void grid_sync()
{
    __syncthreads();
    if (threadIdx.x == 0) {
        unsigned int gen;
        asm volatile("ld.acquire.gpu.global.u32 %0, [%1];"
                     : "=r"(gen) : "l"(&g_gen));
        unsigned int old;
        asm volatile("atom.release.gpu.global.add.u32 %0, [%1], 1;"
                     : "=r"(old) : "l"(&g_count));
        if (old == NBLK - 1) {
            asm volatile("st.relaxed.gpu.global.u32 [%0], %1;"
                         :: "l"(&g_count), "r"(0u));
            asm volatile("st.release.gpu.global.u32 [%0], %1;"
                         :: "l"(&g_gen), "r"(gen + 1));
        } else {
            unsigned int v;
            do {
                asm volatile("ld.acquire.gpu.global.u32 %0, [%1];"
                             : "=r"(v) : "l"(&g_gen));
            } while (v == gen);
        }
    }
    __syncthreads();
}

// ---------------------------------------------------------------------------
// Persistent recurrence. Block b owns hidden indices [16b,16b+16).
// p is BLOCK-LOCAL (full vector in smem, rolled redundantly by every block);
// only gates (z, ht) are exchanged globally. Two timesteps per grid barrier.
// Matvec: K split across warp halves (warps 0-7: K[0:1024), 8-15: K[1024:2048)),
// warp wp handles half-rows wp, wp+8 (z rows) and wp+16, wp+24 (ht rows).
// ---------------------------------------------------------------------------
__global__ __launch_bounds__(NTH, 1) void gru_recurrence(
    const float* __restrict__ Uz, const float* __restrict__ Uh,
    const float* __restrict__ bz,
    const float* __restrict__ Wout,
    const float* __restrict__ zt0, const float* __restrict__ htilde0,
    const float* __restrict__ hprev0,
    float* __restrict__ out)
{
    extern __shared__ float sm[];
    float* smU   = sm;                   // NSTAGE * NH
    float* ps    = sm + NSTAGE * NH;     // NH : persistent local copy of p
    float* part0 = ps + NH;              // 32 partials, K-half 0
    float* part1 = part0 + 32;           // 32 partials, K-half 1

    const int tid  = threadIdx.x;
    const int w    = tid >> 5;
    const int lane = tid & 31;
    const int wp   = w & 7;              // row-group id
    const int kh   = w >> 3;             // K half
    const int b    = blockIdx.x;
    const int I0   = b * HPB;

    // Pin NSTAGE matvec rows into SMEM. Row s: s<16 -> Uz[I0+s], else Uh[I0+s-16].
    for (int s = 0; s < NSTAGE; s++) {
        const float* src = (s < 16) ? (Uz + (size_t)(I0 + s) * NH)
                                    : (Uh + (size_t)(I0 + s - 16) * NH);
        for (int i = tid; i < NH / 4; i += NTH)
            ((float4*)(smU + (size_t)s * NH))[i] = ((const float4*)src)[i];
    }
    // p_0 = hprev0 (block-local full copy)
    float4* ps4 = (float4*)ps;
    ps4[tid] = ((const float4*)hprev0)[tid];

    const float bzv = (lane < 16) ? __ldg(bz + I0 + lane) : 0.f;

    // Per-warp row pointers (K-half slice)
    const int s3 = wp + 24;                       // only it=3 can be residual
    const bool resid = (s3 >= NSTAGE);
    const float4* r0 = (const float4*)(smU + (size_t)(wp)      * NH + kh * 1024);
    const float4* r1 = (const float4*)(smU + (size_t)(wp + 8)  * NH + kh * 1024);
    const float4* r2 = (const float4*)(smU + (size_t)(wp + 16) * NH + kh * 1024);
    const float4* r3s = resid
        ? (const float4*)(Uh + (size_t)(I0 + s3 - 16) * NH + kh * 1024)
        : (const float4*)(smU + (size_t)s3 * NH + kh * 1024);

    __syncthreads();

    // ---- matvec over current smem p, producing gate generation -> buf ----
    auto matvec_gates = [&](int buf, float xv) {
        // residual U row prefetch (constant data; overlaps p reg loads)
        float4 upre[8];
        if (resid) {
            #pragma unroll
            for (int j = 0; j < 8; j++) upre[j] = __ldg(r3s + j * 32 + lane);
        }
        float4 preg[8];
        #pragma unroll
        for (int j = 0; j < 8; j++) preg[j] = ps4[kh * 256 + j * 32 + lane];

        float a0 = 0.f, a1 = 0.f, a2 = 0.f, a3 = 0.f;
        #pragma unroll
        for (int j = 0; j < 8; j++) {
            float4 p = preg[j];
            float4 u;
            u = r0[j * 32 + lane];
            a0 += u.x * p.x + u.y * p.y + u.z * p.z + u.w * p.w;
            u = r1[j * 32 + lane];
            a1 += u.x * p.x + u.y * p.y + u.z * p.z + u.w * p.w;
            u = r2[j * 32 + lane];
            a2 += u.x * p.x + u.y * p.y + u.z * p.z + u.w * p.w;
            u = resid ? upre[j] : r3s[j * 32 + lane];
            a3 += u.x * p.x + u.y * p.y + u.z * p.z + u.w * p.w;
        }
        #pragma unroll
        for (int off = 16; off; off >>= 1) {
            a0 += __shfl_xor_sync(0xffffffffu, a0, off);
            a1 += __shfl_xor_sync(0xffffffffu, a1, off);
            a2 += __shfl_xor_sync(0xffffffffu, a2, off);
            a3 += __shfl_xor_sync(0xffffffffu, a3, off);
        }
        if (lane == 0) {
            float* pt = kh ? part1 : part0;
            pt[wp]      = a0;
            pt[wp + 8]  = a1;
            pt[wp + 16] = a2;
            pt[wp + 24] = a3;
        }
        __syncthreads();
        // Gate warp: lane<16 -> z row I0+lane; lane>=16 -> ht row I0+lane-16
        if (tid < 32) {
            float v = part0[tid] + part1[tid];
            if (tid < 16) {
                float pre = xv + v + bzv;
                g_Zb[buf][I0 + tid] = 1.f / (1.f + expf(-pre));
            } else {
                g_HTb[buf][I0 + tid - 16] = tanhf(xv + v);
            }
        }
    };

    // ---- supersteps: 2 timesteps per grid barrier ----
    for (int m = 0; m < T_STEPS / 2; m++) {
        const int t = 2 * m;

        // Prefetch gate generations t-1 (roll A) and t (roll B) immediately.
        float4 zA, hA, zB, hB;
        if (m > 0) {
            const int bA = (t - 1) & 3;
            zA = __ldcg((const float4*)g_Zb[bA]  + tid);
            hA = __ldcg((const float4*)g_HTb[bA] + tid);
            const int bB = t & 3;
            zB = __ldcg((const float4*)g_Zb[bB]  + tid);
            hB = __ldcg((const float4*)g_HTb[bB] + tid);
        } else {
            zB = ((const float4*)zt0)[tid];
            hB = ((const float4*)htilde0)[tid];
        }
        // x projections for the two matvecs (gate warp only)
        float xv0 = 0.f, xv1 = 0.f;
        if (tid < 32) {
            if (tid < 16) {
                xv0 = __ldg(&g_XZ[(size_t)t * NH + I0 + tid]);
                xv1 = __ldg(&g_XZ[(size_t)(t + 1) * NH + I0 + tid]);
            } else {
                xv0 = __ldg(&g_XH[(size_t)t * NH + I0 + tid - 16]);
                xv1 = __ldg(&g_XH[(size_t)(t + 1) * NH + I0 + tid - 16]);
            }
        }

        // Roll A: p_t = (1-z_{t-1})*p_{t-1} + z_{t-1}*ht_{t-1}  (skip at m=0)
        if (m > 0) {
            float4 p = ps4[tid];
            p.x = (1.f - zA.x) * p.x + zA.x * hA.x;
            p.y = (1.f - zA.y) * p.y + zA.y * hA.y;
            p.z = (1.f - zA.z) * p.z + zA.z * hA.z;
            p.w = (1.f - zA.w) * p.w + zA.w * hA.w;
            ps4[tid] = p;
            __syncthreads();
        }

        // Matvec over p_t -> gates gen t+1
        matvec_gates((t + 1) & 3, xv0);
        __syncthreads();

        // Roll B: p_{t+1} = (1-z_t)*p_t + z_t*ht_t
        {
            float4 p = ps4[tid];
            p.x = (1.f - zB.x) * p.x + zB.x * hB.x;
            p.y = (1.f - zB.y) * p.y + zB.y * hB.y;
            p.z = (1.f - zB.z) * p.z + zB.z * hB.z;
            p.w = (1.f - zB.w) * p.w + zB.w * hB.w;
            ps4[tid] = p;
        }
        __syncthreads();

        // Matvec over p_{t+1} -> gates gen t+2
        matvec_gates((t + 2) & 3, xv1);

        // Make gate STGs visible, then barrier
        if (tid < 32) __threadfence();
        grid_sync();
    }

    // Final roll: p_1024 = (1-z_1023)*p_1023 + z_1023*ht_1023
    {
        const int bF = (T_STEPS - 1) & 3;
        float4 z = __ldcg((const float4*)g_Zb[bF]  + tid);
        float4 h = __ldcg((const float4*)g_HTb[bF] + tid);
        float4 p = ps4[tid];
        p.x = (1.f - z.x) * p.x + z.x * h.x;
        p.y = (1.f - z.y) * p.y + z.y * h.y;
        p.z = (1.f - z.z) * p.z + z.z * h.z;
        p.w = (1.f - z.w) * p.w + z.w * h.w;
        ps4[tid] = p;
    }
    __syncthreads();

    // Logits: warp gw = b*16 + w covers 1000 rows (p from local smem)
    {
        int gw = b * 16 + w;
        if (gw < CATS) {
            const float4* u4 = (const float4*)(Wout + (size_t)gw * NH);
            float acc = 0.f;
            #pragma unroll
            for (int j = 0; j < 16; j++) {
                float4 u = __ldg(u4 + j * 32 + lane);
                float4 p = ps4[j * 32 + lane];
                acc += u.x * p.x + u.y * p.y + u.z * p.z + u.w * p.w;
            }
            #pragma unroll
            for (int off = 16; off; off >>= 1)
                acc += __shfl_xor_sync(0xffffffffu, acc, off);
            if (lane == 0) g_LOGITS[gw] = acc;
        }
    }
    if (tid < 32) __threadfence();
    grid_sync();

    // Softmax in block 0 (reduction buffer reuses ps)
    if (b == 0) {
        float* red = ps;
        float lm = -1e30f;
        for (int c = tid; c < CATS; c += NTH) lm = fmaxf(lm, __ldcg(&g_LOGITS[c]));
        __syncthreads();
        red[tid] = lm; __syncthreads();
        for (int o = NTH / 2; o; o >>= 1) {
            if (tid < o) red[tid] = fmaxf(red[tid], red[tid + o]);
            __syncthreads();
        }
        float mx = red[0]; __syncthreads();
        float ls = 0.f;
        for (int c = tid; c < CATS; c += NTH) ls += expf(__ldcg(&g_LOGITS[c]) - mx);
        red[tid] = ls; __syncthreads();
        for (int o = NTH / 2; o; o >>= 1) {
            if (tid < o) red[tid] += red[tid + o];
            __syncthreads();
        }
        float inv = 1.f / red[0];
        for (int c = tid; c < CATS; c += NTH)
            out[c] = expf(__ldcg(&g_LOGITS[c]) - mx) * inv;
    }
}

// ---------------------------------------------------------------------------
extern "C" void kernel_launch(void* const* d_in, const int* in_sizes, int n_in,
                              void* d_out, int out_size)
{
    const float* x       = (const float*)d_in[0];
    const float* Wh      = (const float*)d_in[1];
    const float* Wz      = (const float*)d_in[2];
    // d_in[3] = Wr, d_in[7] = Ur, d_in[8] = br: dead code in reference
    const float* Uh      = (const float*)d_in[4];
    const float* Uz      = (const float*)d_in[5];
    const float* bz      = (const float*)d_in[6];
    const float* Wout    = (const float*)d_in[9];
    // d_in[10] = h0: never read by the reference recurrence
    const float* zt0     = (const float*)d_in[11];
    const float* htilde0 = (const float*)d_in[12];
    const float* hprev0  = (const float*)d_in[13];
    float* out = (float*)d_out;

    dim3 ggrid((NH * 2) / GBN, T_STEPS / GBM);
    gemm_xproj<<<ggrid, 256>>>(x, Wz, Wh);

    cudaFuncSetAttribute(gru_recurrence,
                         cudaFuncAttributeMaxDynamicSharedMemorySize, SMEM_BYTES);
    gru_recurrence<<<NBLK, NTH, SMEM_BYTES>>>(Uz, Uh, bz, Wout,
                                              zt0, htilde0, hprev0, out);
}